// round 16
// baseline (speedup 1.0000x reference)
#include <cuda_runtime.h>

#define Bv 128
#define Tv 1024
#define Nv 64
#define U 8
#define TPB 32

// Scratch (no cudaMalloc allowed). g_ctr wraps back to 0 every full run -> graph-safe.
__device__ float g_loss[Bv];
__device__ unsigned g_ctr = 0;

#define FMA_X2(d, a, b, c) \
  asm("fma.rn.f32x2 %0, %1, %2, %3;" : "=l"(d) : "l"(a), "l"(b), "l"(c))
#define ADD_X2(d, a, b) \
  asm("add.rn.f32x2 %0, %1, %2;" : "=l"(d) : "l"(a), "l"(b))
#define MUL_X2(d, a, b) \
  asm("mul.rn.f32x2 %0, %1, %2;" : "=l"(d) : "l"(a), "l"(b))
#define PACK2(d, lo, hi) \
  asm("mov.b64 %0, {%1, %2};" : "=l"(d) : "f"(lo), "f"(hi))
#define UNPACK2(lo, hi, s) \
  asm("mov.b64 {%0, %1}, %2;" : "=f"(lo), "=f"(hi) : "l"(s))

__global__ __launch_bounds__(TPB) void crf_kernel(
    const float* __restrict__ pot, const int* __restrict__ tags,
    const int* __restrict__ seqlen, const float* __restrict__ K,
    const float* __restrict__ w, float* __restrict__ out) {
  const int b = blockIdx.x;
  const int j = threadIdx.x;           // 0..31; owns states 2j, 2j+1
  const int s0 = 2 * j;
  const int s1 = 2 * j + 1;
  const int L = seqlen[b];

  __shared__ float Ksh[Nv * 65];                 // padded
  __shared__ __align__(16) float fbuf[2][Nv];    // ping-pong scaled forward vector

  const float* potb = pot + (long)b * Tv * Nv;
  const int* tagb = tags + b * Tv;

  for (int idx = j; idx < Nv * Nv; idx += TPB) {
    int row = idx >> 6, col = idx & 63;
    Ksh[row * 65 + col] = K[idx];
  }
  __syncwarp();

  // ---- sequence score: 32 t's per thread, batched 8 for MLP ----
  float sc = 0.f;
  for (int base = 0; base < 32; base += 8) {
    int tg[8], tp[8];
    float pv[8];
#pragma unroll
    for (int u = 0; u < 8; u++) {
      int t = j + TPB * (base + u);
      tg[u] = tagb[t];
      tp[u] = tagb[t > 0 ? t - 1 : 0];
    }
#pragma unroll
    for (int u = 0; u < 8; u++) pv[u] = potb[(j + TPB * (base + u)) * Nv + tg[u]];
#pragma unroll
    for (int u = 0; u < 8; u++) {
      int t = j + TPB * (base + u);
      if (t < L) {
        sc += pv[u];
        if (t >= 1) sc += Ksh[tp[u] * 65 + tg[u]];
      }
    }
  }
#pragma unroll
  for (int o = 16; o > 0; o >>= 1) sc += __shfl_xor_sync(0xffffffffu, sc, o);
  float sscore = sc;                     // lane-uniform

  // ---- exp(K) for columns s0 and s1, packed f32x2 pairs along i ----
  unsigned long long eKa[32], eKb[32];
#pragma unroll
  for (int p = 0; p < 32; p++) {
    float ea0 = __expf(Ksh[(2 * p) * 65 + s0]);
    float ea1 = __expf(Ksh[(2 * p + 1) * 65 + s0]);
    PACK2(eKa[p], ea0, ea1);
    float eb0 = __expf(Ksh[(2 * p) * 65 + s1]);
    float eb1 = __expf(Ksh[(2 * p + 1) * 65 + s1]);
    PACK2(eKb[p], eb0, eb1);
  }

  // ---- init t = 0: f0 = exp(pot0 - C0), C0 = pot[0][0] ----
  float2 a0v = *(const float2*)(potb + s0);
  float C0 = __shfl_sync(0xffffffffu, a0v.x, 0);
  float f0a = __expf(a0v.x - C0);
  float f0b = __expf(a0v.y - C0);
  unsigned long long fj2;
  PACK2(fj2, f0a, f0b);
  *(unsigned long long*)&fbuf[1][s0] = fj2;
  float acc = C0 * 1.4426950408889634f;  // running -log2(c_t); exact from here on
  float2 pc[U];
#pragma unroll
  for (int u = 0; u < U; u++) pc[u] = *(const float2*)(potb + (1 + u) * Nv + s0);
  __syncwarp();

  // ================= main scan: warp-synchronous, NO block barrier =================
  // Chain: STS.64 -> syncwarp(23) -> 16x LDS.128 -> 64 packed FMA -> trees -> MUL_X2.
  // Normalizer is a power of two from f_{t-1,0} exponent bits (pure ALU, exact).
  int tb = 1;
  for (; tb + U <= L; tb += U) {
#pragma unroll
    for (int u = 0; u < U; u++) {
      float e0 = __expf(pc[u].x);        // p_t for my 2 states
      float e1 = __expf(pc[u].y);
      // one prefetch LDG.64 per step (pc[u] free now)
      int tn = tb + U + u; if (tn > L - 1) tn = L - 1;
      pc[u] = *(const float2*)(potb + tn * Nv + s0);

      const int rb = (1 + u) & 1, wb = rb ^ 1;   // tb always odd -> compile-time
      const ulonglong2* e2 = (const ulonglong2*)fbuf[rb];

      ulonglong2 v0 = e2[0];
      float f00, fdd;
      UNPACK2(f00, fdd, v0.x);
      unsigned ebits = __float_as_uint(f00) & 0x7F800000u;
      float r = __uint_as_float(0x7F000000u - ebits);    // 2^-(E-127), exact
      acc += (float)(int)(ebits >> 23) - 127.0f;         // exact
      unsigned long long prr;
      PACK2(prr, e0 * r, e1 * r);

      unsigned long long aA[4] = {0ull, 0ull, 0ull, 0ull};
      unsigned long long aB[4] = {0ull, 0ull, 0ull, 0ull};
      FMA_X2(aA[0], v0.x, eKa[0], aA[0]);
      FMA_X2(aB[0], v0.x, eKb[0], aB[0]);
      FMA_X2(aA[1], v0.y, eKa[1], aA[1]);
      FMA_X2(aB[1], v0.y, eKb[1], aB[1]);
#pragma unroll
      for (int q = 1; q < 16; q++) {
        ulonglong2 v = e2[q];
        FMA_X2(aA[(2 * q) & 3], v.x, eKa[2 * q], aA[(2 * q) & 3]);
        FMA_X2(aB[(2 * q) & 3], v.x, eKb[2 * q], aB[(2 * q) & 3]);
        FMA_X2(aA[(2 * q + 1) & 3], v.y, eKa[2 * q + 1], aA[(2 * q + 1) & 3]);
        FMA_X2(aB[(2 * q + 1) & 3], v.y, eKb[2 * q + 1], aB[(2 * q + 1) & 3]);
      }
      unsigned long long tA0, tA1, sA, tB0, tB1, sB;
      ADD_X2(tA0, aA[0], aA[1]);
      ADD_X2(tA1, aA[2], aA[3]);
      ADD_X2(sA, tA0, tA1);
      ADD_X2(tB0, aB[0], aB[1]);
      ADD_X2(tB1, aB[2], aB[3]);
      ADD_X2(sB, tB0, tB1);
      float al, ah, bl, bh;
      UNPACK2(al, ah, sA);
      UNPACK2(bl, bh, sB);
      unsigned long long sP;
      PACK2(sP, al + ah, bl + bh);
      MUL_X2(fj2, sP, prr);              // (f_t,s0 , f_t,s1)
      *(unsigned long long*)&fbuf[wb][s0] = fj2;
      __syncwarp();
    }
  }

  // ================= tail: < U steps (runs once) =================
#pragma unroll
  for (int u = 0; u < U; u++) {
    const int tt = tb + u;
    if (tt >= L) break;                  // uniform across warp
    const int rb = tt & 1, wb = rb ^ 1;
    float e0 = __expf(pc[u].x);
    float e1 = __expf(pc[u].y);
    const ulonglong2* e2 = (const ulonglong2*)fbuf[rb];

    ulonglong2 v0 = e2[0];
    float f00, fdd;
    UNPACK2(f00, fdd, v0.x);
    unsigned ebits = __float_as_uint(f00) & 0x7F800000u;
    float r = __uint_as_float(0x7F000000u - ebits);
    acc += (float)(int)(ebits >> 23) - 127.0f;
    unsigned long long prr;
    PACK2(prr, e0 * r, e1 * r);

    unsigned long long aA[4] = {0ull, 0ull, 0ull, 0ull};
    unsigned long long aB[4] = {0ull, 0ull, 0ull, 0ull};
    FMA_X2(aA[0], v0.x, eKa[0], aA[0]);
    FMA_X2(aB[0], v0.x, eKb[0], aB[0]);
    FMA_X2(aA[1], v0.y, eKa[1], aA[1]);
    FMA_X2(aB[1], v0.y, eKb[1], aB[1]);
#pragma unroll
    for (int q = 1; q < 16; q++) {
      ulonglong2 v = e2[q];
      FMA_X2(aA[(2 * q) & 3], v.x, eKa[2 * q], aA[(2 * q) & 3]);
      FMA_X2(aB[(2 * q) & 3], v.x, eKb[2 * q], aB[(2 * q) & 3]);
      FMA_X2(aA[(2 * q + 1) & 3], v.y, eKa[2 * q + 1], aA[(2 * q + 1) & 3]);
      FMA_X2(aB[(2 * q + 1) & 3], v.y, eKb[2 * q + 1], aB[(2 * q + 1) & 3]);
    }
    unsigned long long tA0, tA1, sA, tB0, tB1, sB;
    ADD_X2(tA0, aA[0], aA[1]);
    ADD_X2(tA1, aA[2], aA[3]);
    ADD_X2(sA, tA0, tA1);
    ADD_X2(tB0, aB[0], aB[1]);
    ADD_X2(tB1, aB[2], aB[3]);
    ADD_X2(sB, tB0, tB1);
    float al, ah, bl, bh;
    UNPACK2(al, ah, sA);
    UNPACK2(bl, bh, sB);
    unsigned long long sP;
    PACK2(sP, al + ah, bl + bh);
    MUL_X2(fj2, sP, prr);
    *(unsigned long long*)&fbuf[wb][s0] = fj2;
    __syncwarp();
  }

  // ---- finish: logZ = ln2 * (acc + log2(sum_j f_{L-1,j})) ----
  float fa, fb;
  UNPACK2(fa, fb, fj2);
  float se = fa + fb;
#pragma unroll
  for (int o = 16; o > 0; o >>= 1) se += __shfl_xor_sync(0xffffffffu, se, o);

  unsigned old = 0;
  if (j == 0) {
    float logZ = 0.6931471805599453f * (acc + __log2f(se));
    g_loss[b] = -(sscore - logZ) * w[b];
    __threadfence();
    old = atomicInc(&g_ctr, Bv - 1);     // wraps to 0 each full run
  }
  old = __shfl_sync(0xffffffffu, old, 0);
  if (old == (unsigned)(Bv - 1)) {       // last block: fused mean
    float v = 0.f;
#pragma unroll
    for (int k = 0; k < 4; k++) v += __ldcg(&g_loss[j + TPB * k]);
#pragma unroll
    for (int o = 16; o > 0; o >>= 1) v += __shfl_xor_sync(0xffffffffu, v, o);
    if (j == 0) out[0] = v * (1.0f / (float)Bv);
  }
}

extern "C" void kernel_launch(void* const* d_in, const int* in_sizes, int n_in,
                              void* d_out, int out_size) {
  const float* pot    = (const float*)d_in[0];  // [128,1024,64] f32
  const int*   tags   = (const int*)  d_in[1];  // [128,1024] i32
  const int*   seqlen = (const int*)  d_in[2];  // [128] i32
  const float* K      = (const float*)d_in[3];  // [64,64] f32
  const float* w      = (const float*)d_in[4];  // [128] f32
  crf_kernel<<<Bv, TPB>>>(pot, tags, seqlen, K, w, (float*)d_out);
}